// round 1
// baseline (speedup 1.0000x reference)
#include <cuda_runtime.h>
#include <math.h>

// Problem constants
#define BN  8
#define SEQ 2048
#define DIN 1024
#define DKc 1024
#define DVc 1024

// Scratch (allocation-free rule: __device__ globals)
__device__ float g_Q [(size_t)BN * SEQ * DKc];   //  64 MB
__device__ float g_K [(size_t)BN * SEQ * DKc];   //  64 MB
__device__ float g_V [(size_t)BN * SEQ * DVc];   //  64 MB
__device__ float g_Sc[(size_t)BN * SEQ * SEQ];   // 128 MB

// ---------------------------------------------------------------------------
// Generic 128x128x8 register-blocked SGEMM.
//   C[M,N] = alpha * A[M,K] * op(B) (+ bias[N])
//   B_TRANS=true : B is [N,K] row-major (K-major)  -> C = A * B^T
//   B_TRANS=false: B is [K,N] row-major            -> C = A * B
// All dims assumed multiples of the tile (true for this problem).
// blockIdx.z = batch, with explicit batch strides.
// ---------------------------------------------------------------------------
template <bool B_TRANS, bool BIAS>
__global__ __launch_bounds__(256, 2)
void gemm_k(const float* __restrict__ A, const float* __restrict__ Bm,
            const float* __restrict__ bias, float* __restrict__ C,
            int M, int N, int K,
            long long sA, long long sB, long long sC, float alpha)
{
    A  += (long long)blockIdx.z * sA;
    Bm += (long long)blockIdx.z * sB;
    C  += (long long)blockIdx.z * sC;

    __shared__ float As[8][128];
    __shared__ float Bs[8][128];

    const int tid = threadIdx.x;
    const int tx  = tid & 15;        // 0..15 -> N direction (8 cols each)
    const int ty  = tid >> 4;        // 0..15 -> M direction (8 rows each)
    const int m0  = blockIdx.y * 128;
    const int n0  = blockIdx.x * 128;

    // load-index helpers
    const int lr = tid >> 1;         // 0..127 row within tile
    const int lc = (tid & 1) << 2;   // 0 or 4 (k offset, float4)
    const int br = tid >> 5;         // 0..7   k row (B non-trans)
    const int bc = (tid & 31) << 2;  // 0..124 n col (B non-trans)

    float acc[8][8];
#pragma unroll
    for (int i = 0; i < 8; ++i)
#pragma unroll
        for (int j = 0; j < 8; ++j) acc[i][j] = 0.0f;

    const float* Aptr = A + (long long)(m0 + lr) * K + lc;
    const float* Bptr = B_TRANS ? (Bm + (long long)(n0 + lr) * K + lc)
                                : (Bm + (long long)br * N + n0 + bc);

    for (int k0 = 0; k0 < K; k0 += 8) {
        float4 av = *(const float4*)(Aptr + k0);
        As[lc + 0][lr] = av.x;
        As[lc + 1][lr] = av.y;
        As[lc + 2][lr] = av.z;
        As[lc + 3][lr] = av.w;
        if (B_TRANS) {
            float4 bv = *(const float4*)(Bptr + k0);
            Bs[lc + 0][lr] = bv.x;
            Bs[lc + 1][lr] = bv.y;
            Bs[lc + 2][lr] = bv.z;
            Bs[lc + 3][lr] = bv.w;
        } else {
            float4 bv = *(const float4*)(Bptr + (long long)k0 * N);
            *(float4*)&Bs[br][bc] = bv;
        }
        __syncthreads();

#pragma unroll
        for (int kk = 0; kk < 8; ++kk) {
            float a[8], b[8];
            *(float4*)&a[0] = *(const float4*)&As[kk][ty * 8];
            *(float4*)&a[4] = *(const float4*)&As[kk][ty * 8 + 4];
            *(float4*)&b[0] = *(const float4*)&Bs[kk][tx * 8];
            *(float4*)&b[4] = *(const float4*)&Bs[kk][tx * 8 + 4];
#pragma unroll
            for (int i = 0; i < 8; ++i)
#pragma unroll
                for (int j = 0; j < 8; ++j)
                    acc[i][j] = fmaf(a[i], b[j], acc[i][j]);
        }
        __syncthreads();
    }

    // epilogue
#pragma unroll
    for (int i = 0; i < 8; ++i) {
        const long long row = m0 + ty * 8 + i;
        float* crow = C + row * N + n0 + tx * 8;
#pragma unroll
        for (int j4 = 0; j4 < 8; j4 += 4) {
            float4 v;
            v.x = acc[i][j4 + 0] * alpha;
            v.y = acc[i][j4 + 1] * alpha;
            v.z = acc[i][j4 + 2] * alpha;
            v.w = acc[i][j4 + 3] * alpha;
            if (BIAS) {
                const float* bb = bias + n0 + tx * 8 + j4;
                v.x += bb[0]; v.y += bb[1]; v.z += bb[2]; v.w += bb[3];
            }
            *(float4*)(crow + j4) = v;
        }
    }
}

// ---------------------------------------------------------------------------
// Row softmax over rows of length SEQ (2048). One block of 256 threads per
// row; 8 elems/thread kept in registers; max and sum via shuffle + smem.
// ---------------------------------------------------------------------------
__global__ __launch_bounds__(256)
void softmax_k(float* __restrict__ Sc)
{
    float* p = Sc + (long long)blockIdx.x * SEQ;
    const int tid = threadIdx.x;

    float v[8];
    float mx = -1e30f;
#pragma unroll
    for (int i = 0; i < 8; ++i) {
        v[i] = p[tid + i * 256];
        mx = fmaxf(mx, v[i]);
    }

    __shared__ float redm[8];
    __shared__ float reds[8];

#pragma unroll
    for (int o = 16; o > 0; o >>= 1)
        mx = fmaxf(mx, __shfl_xor_sync(0xffffffffu, mx, o));
    if ((tid & 31) == 0) redm[tid >> 5] = mx;
    __syncthreads();
    mx = redm[0];
#pragma unroll
    for (int i = 1; i < 8; ++i) mx = fmaxf(mx, redm[i]);

    float s = 0.0f;
#pragma unroll
    for (int i = 0; i < 8; ++i) { v[i] = __expf(v[i] - mx); s += v[i]; }

#pragma unroll
    for (int o = 16; o > 0; o >>= 1)
        s += __shfl_xor_sync(0xffffffffu, s, o);
    if ((tid & 31) == 0) reds[tid >> 5] = s;
    __syncthreads();
    s = 0.0f;
#pragma unroll
    for (int i = 0; i < 8; ++i) s += reds[i];

    const float inv = 1.0f / s;
#pragma unroll
    for (int i = 0; i < 8; ++i) p[tid + i * 256] = v[i] * inv;
}

// ---------------------------------------------------------------------------
extern "C" void kernel_launch(void* const* d_in, const int* in_sizes, int n_in,
                              void* d_out, int out_size)
{
    (void)in_sizes; (void)n_in; (void)out_size;
    const float* q  = (const float*)d_in[0];
    const float* kx = (const float*)d_in[1];
    const float* vx = (const float*)d_in[2];
    const float* Wq = (const float*)d_in[3];
    const float* bq = (const float*)d_in[4];
    const float* Wk = (const float*)d_in[5];
    const float* bk = (const float*)d_in[6];
    const float* Wv = (const float*)d_in[7];
    const float* bv = (const float*)d_in[8];
    float* out = (float*)d_out;

    float *gQ, *gK, *gV, *gS;
    cudaGetSymbolAddress((void**)&gQ, g_Q);
    cudaGetSymbolAddress((void**)&gK, g_K);
    cudaGetSymbolAddress((void**)&gV, g_V);
    cudaGetSymbolAddress((void**)&gS, g_Sc);

    const int M1 = BN * SEQ;   // 16384 flattened rows
    dim3 blk(256);

    // Projections: C = X * W^T + b   (W is [out,in], K-major -> B_TRANS)
    gemm_k<true, true><<<dim3(DKc / 128, M1 / 128, 1), blk>>>(
        q,  Wq, bq, gQ, M1, DKc, DIN, 0, 0, 0, 1.0f);
    gemm_k<true, true><<<dim3(DKc / 128, M1 / 128, 1), blk>>>(
        kx, Wk, bk, gK, M1, DKc, DIN, 0, 0, 0, 1.0f);
    gemm_k<true, true><<<dim3(DVc / 128, M1 / 128, 1), blk>>>(
        vx, Wv, bv, gV, M1, DVc, DIN, 0, 0, 0, 1.0f);

    // Scores: S = (Q * K^T) / sqrt(DK), batched over BN
    gemm_k<true, false><<<dim3(SEQ / 128, SEQ / 128, BN), blk>>>(
        gQ, gK, nullptr, gS, SEQ, SEQ, DKc,
        (long long)SEQ * DKc, (long long)SEQ * DKc, (long long)SEQ * SEQ,
        0.03125f /* 1/sqrt(1024) */);

    // Row softmax over all BN*SEQ rows
    softmax_k<<<BN * SEQ, 256>>>(gS);

    // Output: O = P * V, batched over BN
    gemm_k<false, false><<<dim3(DVc / 128, SEQ / 128, BN), blk>>>(
        gS, gV, nullptr, out, SEQ, DVc, SEQ,
        (long long)SEQ * SEQ, (long long)SEQ * DVc, (long long)SEQ * DVc,
        1.0f);
}

// round 3
// speedup vs baseline: 5.2018x; 5.2018x over previous
#include <cuda_runtime.h>
#include <cuda_bf16.h>
#include <cstdint>

// ---------------------------------------------------------------------------
// Problem constants
// ---------------------------------------------------------------------------
#define BN   8
#define SEQ  2048
#define DIN  1024
#define DM   1024
#define NTOK (BN*SEQ)          // 16384

// ---------------------------------------------------------------------------
// Scratch (__device__ globals; allocation-free rule)
// ---------------------------------------------------------------------------
__device__ __nv_bfloat16 g_Xq_h[(size_t)NTOK*DIN];
__device__ __nv_bfloat16 g_Xq_l[(size_t)NTOK*DIN];
__device__ __nv_bfloat16 g_Xk_h[(size_t)NTOK*DIN];
__device__ __nv_bfloat16 g_Xk_l[(size_t)NTOK*DIN];
__device__ __nv_bfloat16 g_Xv_h[(size_t)NTOK*DIN];
__device__ __nv_bfloat16 g_Xv_l[(size_t)NTOK*DIN];
__device__ __nv_bfloat16 g_Wq_h[(size_t)DM*DIN];
__device__ __nv_bfloat16 g_Wq_l[(size_t)DM*DIN];
__device__ __nv_bfloat16 g_Wk_h[(size_t)DM*DIN];
__device__ __nv_bfloat16 g_Wk_l[(size_t)DM*DIN];
__device__ __nv_bfloat16 g_Wv_h[(size_t)DM*DIN];
__device__ __nv_bfloat16 g_Wv_l[(size_t)DM*DIN];
__device__ __nv_bfloat16 g_Q_h [(size_t)NTOK*DM];
__device__ __nv_bfloat16 g_Q_l [(size_t)NTOK*DM];
__device__ __nv_bfloat16 g_K_h [(size_t)NTOK*DM];
__device__ __nv_bfloat16 g_K_l [(size_t)NTOK*DM];
__device__ __nv_bfloat16 g_Vt_h[(size_t)BN*DM*SEQ];     // [b][v][s]
__device__ __nv_bfloat16 g_Vt_l[(size_t)BN*DM*SEQ];
__device__ float         g_S  [(size_t)BN*SEQ*SEQ];
__device__ __nv_bfloat16 g_P_h[(size_t)BN*SEQ*SEQ];
__device__ __nv_bfloat16 g_P_l[(size_t)BN*SEQ*SEQ];

// ---------------------------------------------------------------------------
// Helpers available on base compute_103
// ---------------------------------------------------------------------------
__device__ __forceinline__ uint32_t smem_u32(const void* p) {
    uint32_t a;
    asm("{ .reg .u64 t; cvta.to.shared.u64 t, %1; cvt.u32.u64 %0, t; }"
        : "=r"(a) : "l"(p));
    return a;
}
__device__ __forceinline__ void cp16(uint32_t dst, const void* src) {
    asm volatile("cp.async.cg.shared.global [%0], [%1], 16;" :: "r"(dst), "l"(src));
}
#define CP_COMMIT()  asm volatile("cp.async.commit_group;" ::: "memory")
#define CP_WAIT(N)   asm volatile("cp.async.wait_group %0;" :: "n"(N) : "memory")

__device__ __forceinline__ void mma16816(float* c, const uint32_t* a,
                                         uint32_t b0, uint32_t b1) {
    asm volatile(
        "mma.sync.aligned.m16n8k16.row.col.f32.bf16.bf16.f32 "
        "{%0,%1,%2,%3}, {%4,%5,%6,%7}, {%8,%9}, {%0,%1,%2,%3};"
        : "+f"(c[0]), "+f"(c[1]), "+f"(c[2]), "+f"(c[3])
        : "r"(a[0]), "r"(a[1]), "r"(a[2]), "r"(a[3]), "r"(b0), "r"(b1));
}

__device__ __forceinline__ void split2(float v, __nv_bfloat16& h, __nv_bfloat16& l) {
    h = __float2bfloat16(v);
    l = __float2bfloat16(v - __bfloat162float(h));
}

// ---------------------------------------------------------------------------
// tcgen05 helpers — ONLY compiled when the build has a compute_103a pass.
// ---------------------------------------------------------------------------
#if defined(__CUDA_ARCH_FEAT_SM103_ALL)
__device__ __forceinline__ uint32_t elect_one_pred() {
    uint32_t pred;
    asm volatile(
        "{\n\t.reg .pred p;\n\t"
        "elect.sync _|p, 0xFFFFFFFF;\n\t"
        "selp.b32 %0, 1, 0, p;\n\t}"
        : "=r"(pred));
    return pred;
}
#define MBARRIER_INIT(addr, cnt) \
    asm volatile("mbarrier.init.shared.b64 [%0], %1;" :: "r"((uint32_t)(addr)), "r"((uint32_t)(cnt)) : "memory")
#define MBARRIER_WAIT_PARITY(mbar, par) do { \
    uint32_t _m = (uint32_t)(mbar), _p = (uint32_t)(par), _d; \
    asm volatile("{\n\t.reg .pred p;\n\t" \
        "mbarrier.try_wait.parity.acquire.cta.shared::cta.b64 p, [%1], %2;\n\t" \
        "selp.b32 %0, 1, 0, p;\n\t}" : "=r"(_d) : "r"(_m), "r"(_p) : "memory"); \
    if (!_d) { \
        asm volatile("{\n\t.reg .pred P1;\n\t" \
            "WL_%=:\n\t" \
            "mbarrier.try_wait.parity.acquire.cta.shared::cta.b64 P1, [%0], %1, 0x989680;\n\t" \
            "@P1 bra.uni WD_%=;\n\tbra.uni WL_%=;\n\tWD_%=:\n\t}" \
            :: "r"(_m), "r"(_p) : "memory"); \
    } \
} while (0)
#define TCGEN05_ALLOC(a, n) \
    asm volatile("tcgen05.alloc.cta_group::1.sync.aligned.shared::cta.b32 [%0], %1;" \
        :: "r"((uint32_t)(a)), "r"((uint32_t)(n)) : "memory")
#define TCGEN05_RELINQUISH() \
    asm volatile("tcgen05.relinquish_alloc_permit.cta_group::1.sync.aligned;")
#define TCGEN05_DEALLOC(t, n) \
    asm volatile("tcgen05.dealloc.cta_group::1.sync.aligned.b32 %0, %1;" :: "r"(t), "r"((uint32_t)(n)))
#define TCGEN05_COMMIT(m) \
    asm volatile("tcgen05.commit.cta_group::1.mbarrier::arrive::one.shared::cluster.b64 [%0];" \
        :: "r"((uint32_t)(m)) : "memory")
#define TCGEN05_WAIT_LD()    asm volatile("tcgen05.wait::ld.sync.aligned;" ::: "memory")
#define TCGEN05_FENCE_AFTER() asm volatile("tcgen05.fence::after_thread_sync;" ::: "memory")
#define FENCE_PROXY_ASYNC()  asm volatile("fence.proxy.async.shared::cta;" ::: "memory")
#define TCGEN05_LD_32X32B_X32(r, ta) \
    asm volatile( \
        "tcgen05.ld.sync.aligned.32x32b.x32.b32 " \
        "{%0, %1, %2, %3, %4, %5, %6, %7, " \
        " %8, %9, %10, %11, %12, %13, %14, %15, " \
        " %16, %17, %18, %19, %20, %21, %22, %23, " \
        " %24, %25, %26, %27, %28, %29, %30, %31}, [%32];" \
        : "=r"((r)[0]),  "=r"((r)[1]),  "=r"((r)[2]),  "=r"((r)[3]), \
          "=r"((r)[4]),  "=r"((r)[5]),  "=r"((r)[6]),  "=r"((r)[7]), \
          "=r"((r)[8]),  "=r"((r)[9]),  "=r"((r)[10]), "=r"((r)[11]), \
          "=r"((r)[12]), "=r"((r)[13]), "=r"((r)[14]), "=r"((r)[15]), \
          "=r"((r)[16]), "=r"((r)[17]), "=r"((r)[18]), "=r"((r)[19]), \
          "=r"((r)[20]), "=r"((r)[21]), "=r"((r)[22]), "=r"((r)[23]), \
          "=r"((r)[24]), "=r"((r)[25]), "=r"((r)[26]), "=r"((r)[27]), \
          "=r"((r)[28]), "=r"((r)[29]), "=r"((r)[30]), "=r"((r)[31]) \
        : "r"(ta))
static constexpr uint64_t SMEM_DESC_BASE_SW128 =
    (uint64_t(2)  << 61) | (uint64_t(1) << 46) | (uint64_t(64) << 32) | (uint64_t(1) << 16);
#define MAKE_SMEM_DESC(ba) (SMEM_DESC_BASE_SW128 | ((uint64_t)((ba) >> 4) & 0x3FFF))
#define SWZ128(off) ((off) ^ (((off) >> 3) & 0x70))
__device__ __forceinline__ void mma_bf16_ss(uint32_t d, uint64_t ad, uint64_t bd,
                                            uint32_t idesc, bool acc) {
    uint32_t en = acc ? 1u : 0u;
    asm volatile(
        "{\n\t.reg .pred p;\n\t"
        "setp.ne.u32 p, %5, 0;\n\t"
        "tcgen05.mma.cta_group::1.kind::f16 [%0], %1, %2, %3, {%4, %4, %4, %4}, p;\n\t"
        "}"
        :: "r"(d), "l"(ad), "l"(bd), "r"(idesc), "r"(0u), "r"(en)
        : "memory");
}
#endif  // __CUDA_ARCH_FEAT_SM103_ALL

// ---------------------------------------------------------------------------
// GEMM: C[M,N] = alpha * A[M,K] * B[N,K]^T (+bias), split-bf16 3-pass:
//   acc = Ah*Bh + Ah*Bl + Al*Bh      (AlBl dropped, ~2^-16 rel)
// Tile 128x128, 256 threads, grid (N/128, M/128, batch).
// MODE 0: f32 out (alpha)   MODE 1: split bf16 out (+bias)
// MODE 2: split bf16 transposed out (+bias), V -> Vt[b][n][s]
// Body dispatches on arch: tcgen05 (sm_103a cubin) vs mma.sync (base).
// ---------------------------------------------------------------------------
constexpr int SMEM_TOTAL = 1024 + 2 * 65536;   // tcgen05 need (max of both paths)

template <int MODE>
__global__ void __launch_bounds__(256, 1) tc_gemm(
    const __nv_bfloat16* __restrict__ Ah, const __nv_bfloat16* __restrict__ Al,
    const __nv_bfloat16* __restrict__ Bh, const __nv_bfloat16* __restrict__ Bl,
    const float* __restrict__ bias,
    float* __restrict__ Cf,
    __nv_bfloat16* __restrict__ Ch, __nv_bfloat16* __restrict__ Cl,
    int K, int ldc, float alpha,
    size_t sA, size_t sB, size_t sC)
{
    extern __shared__ char smem[];
    const int tid   = threadIdx.x;
    const size_t zb = blockIdx.z;
    const int m0    = blockIdx.y * 128;
    const int n0    = blockIdx.x * 128;
    Ah += zb * sA;  Al += zb * sA;
    Bh += zb * sB;  Bl += zb * sB;

#if defined(__CUDA_ARCH_FEAT_SM103_ALL)
    // ======================= tcgen05 path (sm_103a) ========================
    constexpr int OFF_AH = 0, OFF_AL = 16384, OFF_BH = 32768, OFF_BL = 49152;
    constexpr int STAGE = 65536, DATA = 1024;
    const uint32_t sb = smem_u32(smem);

    if (tid < 32) TCGEN05_ALLOC(sb + 0, 128);
    else if ((tid & 31) == 0 || true) { if (tid >= 32 && (tid & 31) == 0) {} }
    if (tid >= 32 && tid < 64) TCGEN05_RELINQUISH();
    if (tid == 0) { MBARRIER_INIT(sb + 8, 1); MBARRIER_INIT(sb + 16, 1); }
    __syncthreads();
    uint32_t tmem;
    asm volatile("ld.shared.b32 %0, [%1];" : "=r"(tmem) : "r"(sb + 0));

    const int col = tid & 7;       // 16B block within 128B row
    const int rg  = tid >> 3;      // 0..31

    auto load_chunk = [&](int kc, int st) {
        const uint32_t base = sb + DATA + st * STAGE;
        const size_t koff = (size_t)kc * 64 + col * 8;
        const __nv_bfloat16* pah = Ah + (size_t)(m0 + rg) * K + koff;
        const __nv_bfloat16* pal = Al + (size_t)(m0 + rg) * K + koff;
        const __nv_bfloat16* pbh = Bh + (size_t)(n0 + rg) * K + koff;
        const __nv_bfloat16* pbl = Bl + (size_t)(n0 + rg) * K + koff;
#pragma unroll
        for (int i = 0; i < 4; ++i) {
            uint32_t so = SWZ128((rg + 32 * i) * 128 + col * 16);
            cp16(base + OFF_AH + so, pah + (size_t)(32 * i) * K);
            cp16(base + OFF_AL + so, pal + (size_t)(32 * i) * K);
            cp16(base + OFF_BH + so, pbh + (size_t)(32 * i) * K);
            cp16(base + OFF_BL + so, pbl + (size_t)(32 * i) * K);
        }
    };

    constexpr uint32_t IDESC =
        (1u << 4) | (1u << 7) | (1u << 10) | ((128 / 8) << 17) | ((128 / 16) << 24);
    const int NC = K / 64;

    load_chunk(0, 0); CP_COMMIT();
    load_chunk(1, 1); CP_COMMIT();

    int ph[2] = {0, 0};
    for (int c = 0; c < NC; ++c) {
        const int st = c & 1;
        if (c + 1 < NC) { CP_WAIT(1); } else { CP_WAIT(0); }
        FENCE_PROXY_ASYNC();
        __syncthreads();

        if (tid < 32 && elect_one_pred()) {
            TCGEN05_FENCE_AFTER();
            const uint32_t base = sb + DATA + st * STAGE;
            const uint64_t dah = MAKE_SMEM_DESC(base + OFF_AH);
            const uint64_t dal = MAKE_SMEM_DESC(base + OFF_AL);
            const uint64_t dbh = MAKE_SMEM_DESC(base + OFF_BH);
            const uint64_t dbl = MAKE_SMEM_DESC(base + OFF_BL);
#pragma unroll
            for (int ks = 0; ks < 4; ++ks)
                mma_bf16_ss(tmem, dah + ks * 2, dbh + ks * 2, IDESC, !(c == 0 && ks == 0));
#pragma unroll
            for (int ks = 0; ks < 4; ++ks)
                mma_bf16_ss(tmem, dah + ks * 2, dbl + ks * 2, IDESC, true);
#pragma unroll
            for (int ks = 0; ks < 4; ++ks)
                mma_bf16_ss(tmem, dal + ks * 2, dbh + ks * 2, IDESC, true);
            TCGEN05_COMMIT(sb + 8 + 8 * st);
        }
        MBARRIER_WAIT_PARITY(sb + 8 + 8 * st, ph[st]);
        ph[st] ^= 1;
        if (c + 2 < NC) { load_chunk(c + 2, st); CP_COMMIT(); }
    }
    TCGEN05_FENCE_AFTER();

    if (tid < 128) {
        const int w = tid >> 5, lid = tid & 31;
        const int m = m0 + w * 32 + lid;
        for (int j0 = 0; j0 < 128; j0 += 32) {
            uint32_t r[32];
            TCGEN05_LD_32X32B_X32(r, tmem + j0);
            TCGEN05_WAIT_LD();
            if (MODE == 0) {
                float4* dst = (float4*)(Cf + zb * sC + (size_t)m * ldc + n0 + j0);
#pragma unroll
                for (int i = 0; i < 8; ++i) {
                    float4 v;
                    v.x = __uint_as_float(r[4 * i + 0]) * alpha;
                    v.y = __uint_as_float(r[4 * i + 1]) * alpha;
                    v.z = __uint_as_float(r[4 * i + 2]) * alpha;
                    v.w = __uint_as_float(r[4 * i + 3]) * alpha;
                    dst[i] = v;
                }
            } else if (MODE == 1) {
                const size_t rb = (size_t)m * ldc + n0 + j0;
#pragma unroll
                for (int i = 0; i < 32; i += 2) {
                    float v0 = __uint_as_float(r[i])     + bias[n0 + j0 + i];
                    float v1 = __uint_as_float(r[i + 1]) + bias[n0 + j0 + i + 1];
                    __nv_bfloat16 h0, l0, h1, l1;
                    split2(v0, h0, l0); split2(v1, h1, l1);
                    __nv_bfloat162 hp; hp.x = h0; hp.y = h1;
                    __nv_bfloat162 lp; lp.x = l0; lp.y = l1;
                    *(__nv_bfloat162*)(Ch + rb + i) = hp;
                    *(__nv_bfloat162*)(Cl + rb + i) = lp;
                }
            } else {
                const int b  = m >> 11;
                const int sx = m & 2047;
                const size_t bb = (size_t)b * DM * SEQ;
#pragma unroll
                for (int i = 0; i < 32; ++i) {
                    const int n = n0 + j0 + i;
                    float v = __uint_as_float(r[i]) + bias[n];
                    __nv_bfloat16 h, l;
                    split2(v, h, l);
                    Ch[bb + (size_t)n * SEQ + sx] = h;
                    Cl[bb + (size_t)n * SEQ + sx] = l;
                }
            }
        }
    }
    __syncthreads();
    if (tid < 32) TCGEN05_DEALLOC(tmem, 128);

#elif defined(__CUDA_ARCH__)
    // ================= mma.sync fallback (base compute_103) =================
    // smem tiles: rows of 32 bf16 (16 words) padded to 20 words for
    // conflict-free fragment loads. 4 tiles/stage, 2 stages.
    constexpr int STR = 20;                 // words per row
    constexpr int TILE_W = 128 * STR;       // 2560 words
    constexpr int STAGE_W = 4 * TILE_W;     // 10240 words
    const uint32_t sbase = smem_u32(smem);
    const int lane = tid & 31, wid = tid >> 5;
    const int wm = wid >> 1, wn = wid & 1;  // warp grid 4(M) x 2(N)
    const int g = lane >> 2, tg = lane & 3;

    auto load_chunk = [&](int kc, int st) {
        const int q = tid & 3, r0 = tid >> 2;     // q: 16B quarter, r0: 0..63
        const uint32_t dst0 = sbase + st * STAGE_W * 4;
        const size_t koff = (size_t)kc * 32 + q * 8;
#pragma unroll
        for (int i = 0; i < 2; ++i) {
            const int r = r0 + 64 * i;
            const uint32_t ro = (uint32_t)(r * STR + q * 4) * 4;
            cp16(dst0 + 0 * TILE_W * 4 + ro, Ah + (size_t)(m0 + r) * K + koff);
            cp16(dst0 + 1 * TILE_W * 4 + ro, Al + (size_t)(m0 + r) * K + koff);
            cp16(dst0 + 2 * TILE_W * 4 + ro, Bh + (size_t)(n0 + r) * K + koff);
            cp16(dst0 + 3 * TILE_W * 4 + ro, Bl + (size_t)(n0 + r) * K + koff);
        }
    };

    float acc[2][8][4];
#pragma unroll
    for (int a = 0; a < 2; ++a)
#pragma unroll
        for (int b = 0; b < 8; ++b)
#pragma unroll
            for (int c = 0; c < 4; ++c) acc[a][b][c] = 0.0f;

    const int NC = K / 32;
    load_chunk(0, 0); CP_COMMIT();

    for (int c = 0; c < NC; ++c) {
        const int st = c & 1;
        if (c + 1 < NC) { load_chunk(c + 1, st ^ 1); CP_COMMIT(); CP_WAIT(1); }
        else           { CP_WAIT(0); }
        __syncthreads();

        const uint32_t* s0 = (const uint32_t*)smem + st * STAGE_W;
#pragma unroll
        for (int ks = 0; ks < 2; ++ks) {
            uint32_t ah[2][4], al[2][4];
#pragma unroll
            for (int mt = 0; mt < 2; ++mt) {
                const int rb = wm * 32 + mt * 16;
                const uint32_t* pa = s0 + (rb + g) * STR + ks * 8 + tg;
                ah[mt][0] = pa[0];           ah[mt][2] = pa[4];
                ah[mt][1] = pa[8 * STR];     ah[mt][3] = pa[8 * STR + 4];
                const uint32_t* pl = pa + TILE_W;
                al[mt][0] = pl[0];           al[mt][2] = pl[4];
                al[mt][1] = pl[8 * STR];     al[mt][3] = pl[8 * STR + 4];
            }
#pragma unroll
            for (int nt = 0; nt < 8; ++nt) {
                const int nb = wn * 64 + nt * 8;
                const uint32_t* pb = s0 + 2 * TILE_W + (nb + g) * STR + ks * 8 + tg;
                const uint32_t bh0 = pb[0], bh1 = pb[4];
                const uint32_t* pbl = pb + TILE_W;
                const uint32_t bl0 = pbl[0], bl1 = pbl[4];
#pragma unroll
                for (int mt = 0; mt < 2; ++mt) {
                    mma16816(acc[mt][nt], ah[mt], bh0, bh1);
                    mma16816(acc[mt][nt], ah[mt], bl0, bl1);
                    mma16816(acc[mt][nt], al[mt], bh0, bh1);
                }
            }
        }
        __syncthreads();
    }

    // epilogue
#pragma unroll
    for (int mt = 0; mt < 2; ++mt) {
#pragma unroll
        for (int nt = 0; nt < 8; ++nt) {
            const int m1 = m0 + wm * 32 + mt * 16 + g;
            const int m2 = m1 + 8;
            const int n  = n0 + wn * 64 + nt * 8 + tg * 2;
            const float* a = acc[mt][nt];
            if (MODE == 0) {
                float2 v0; v0.x = a[0] * alpha; v0.y = a[1] * alpha;
                float2 v1; v1.x = a[2] * alpha; v1.y = a[3] * alpha;
                *(float2*)(Cf + zb * sC + (size_t)m1 * ldc + n) = v0;
                *(float2*)(Cf + zb * sC + (size_t)m2 * ldc + n) = v1;
            } else if (MODE == 1) {
                const float b0 = bias[n], b1 = bias[n + 1];
                __nv_bfloat16 h0, l0, h1, l1;
                split2(a[0] + b0, h0, l0); split2(a[1] + b1, h1, l1);
                __nv_bfloat162 hp; hp.x = h0; hp.y = h1;
                __nv_bfloat162 lp; lp.x = l0; lp.y = l1;
                *(__nv_bfloat162*)(Ch + (size_t)m1 * ldc + n) = hp;
                *(__nv_bfloat162*)(Cl + (size_t)m1 * ldc + n) = lp;
                split2(a[2] + b0, h0, l0); split2(a[3] + b1, h1, l1);
                hp.x = h0; hp.y = h1; lp.x = l0; lp.y = l1;
                *(__nv_bfloat162*)(Ch + (size_t)m2 * ldc + n) = hp;
                *(__nv_bfloat162*)(Cl + (size_t)m2 * ldc + n) = lp;
            } else {
                const float b0 = bias[n], b1 = bias[n + 1];
#pragma unroll
                for (int e = 0; e < 4; ++e) {
                    const int m = (e < 2) ? m1 : m2;
                    const int nn = n + (e & 1);
                    const float bb_ = (e & 1) ? b1 : b0;
                    const int bidx = m >> 11, sx = m & 2047;
                    __nv_bfloat16 h, l;
                    split2(a[e] + bb_, h, l);
                    const size_t off = (size_t)bidx * DM * SEQ + (size_t)nn * SEQ + sx;
                    Ch[off] = h;
                    Cl[off] = l;
                }
            }
        }
    }
#endif
}

// ---------------------------------------------------------------------------
// f32 -> bf16 hi/lo split
// ---------------------------------------------------------------------------
__global__ void __launch_bounds__(256) split_k(
    const float4* __restrict__ x,
    __nv_bfloat16* __restrict__ h, __nv_bfloat16* __restrict__ l, int n4)
{
    for (int i = blockIdx.x * 256 + threadIdx.x; i < n4; i += gridDim.x * 256) {
        float4 v = x[i];
        __nv_bfloat16 h0, l0, h1, l1, h2, l2, h3, l3;
        split2(v.x, h0, l0); split2(v.y, h1, l1);
        split2(v.z, h2, l2); split2(v.w, h3, l3);
        __nv_bfloat162 ha; ha.x = h0; ha.y = h1;
        __nv_bfloat162 hb; hb.x = h2; hb.y = h3;
        __nv_bfloat162 la; la.x = l0; la.y = l1;
        __nv_bfloat162 lb; lb.x = l2; lb.y = l3;
        *(__nv_bfloat162*)(h + 4 * (size_t)i)     = ha;
        *(__nv_bfloat162*)(h + 4 * (size_t)i + 2) = hb;
        *(__nv_bfloat162*)(l + 4 * (size_t)i)     = la;
        *(__nv_bfloat162*)(l + 4 * (size_t)i + 2) = lb;
    }
}

// ---------------------------------------------------------------------------
// Row softmax over SEQ, emitting split bf16 P
// ---------------------------------------------------------------------------
__global__ void __launch_bounds__(256) softmax_k(
    const float* __restrict__ S,
    __nv_bfloat16* __restrict__ Ph, __nv_bfloat16* __restrict__ Pl)
{
    const float* p = S + (size_t)blockIdx.x * SEQ;
    const int tid = threadIdx.x;

    float v[8];
    float mx = -1e30f;
#pragma unroll
    for (int i = 0; i < 8; ++i) { v[i] = p[tid + i * 256]; mx = fmaxf(mx, v[i]); }

    __shared__ float redm[8], reds[8];
#pragma unroll
    for (int o = 16; o > 0; o >>= 1)
        mx = fmaxf(mx, __shfl_xor_sync(0xffffffffu, mx, o));
    if ((tid & 31) == 0) redm[tid >> 5] = mx;
    __syncthreads();
    mx = redm[0];
#pragma unroll
    for (int i = 1; i < 8; ++i) mx = fmaxf(mx, redm[i]);

    float s = 0.0f;
#pragma unroll
    for (int i = 0; i < 8; ++i) { v[i] = __expf(v[i] - mx); s += v[i]; }
#pragma unroll
    for (int o = 16; o > 0; o >>= 1)
        s += __shfl_xor_sync(0xffffffffu, s, o);
    if ((tid & 31) == 0) reds[tid >> 5] = s;
    __syncthreads();
    s = 0.0f;
#pragma unroll
    for (int i = 0; i < 8; ++i) s += reds[i];

    const float inv = 1.0f / s;
    size_t rb = (size_t)blockIdx.x * SEQ;
#pragma unroll
    for (int i = 0; i < 8; ++i) {
        __nv_bfloat16 h, l;
        split2(v[i] * inv, h, l);
        Ph[rb + tid + i * 256] = h;
        Pl[rb + tid + i * 256] = l;
    }
}

// ---------------------------------------------------------------------------
extern "C" void kernel_launch(void* const* d_in, const int* in_sizes, int n_in,
                              void* d_out, int out_size)
{
    (void)in_sizes; (void)n_in; (void)out_size;
    const float* q  = (const float*)d_in[0];
    const float* kx = (const float*)d_in[1];
    const float* vx = (const float*)d_in[2];
    const float* Wq = (const float*)d_in[3];
    const float* bq = (const float*)d_in[4];
    const float* Wk = (const float*)d_in[5];
    const float* bk = (const float*)d_in[6];
    const float* Wv = (const float*)d_in[7];
    const float* bv = (const float*)d_in[8];
    float* out = (float*)d_out;

    __nv_bfloat16 *Xqh, *Xql, *Xkh, *Xkl, *Xvh, *Xvl;
    __nv_bfloat16 *Wqh, *Wql, *Wkh, *Wkl, *Wvh, *Wvl;
    __nv_bfloat16 *Qh, *Ql, *Kh, *Kl, *Vth, *Vtl, *Ph, *Pl;
    float* Sf;
    cudaGetSymbolAddress((void**)&Xqh, g_Xq_h); cudaGetSymbolAddress((void**)&Xql, g_Xq_l);
    cudaGetSymbolAddress((void**)&Xkh, g_Xk_h); cudaGetSymbolAddress((void**)&Xkl, g_Xk_l);
    cudaGetSymbolAddress((void**)&Xvh, g_Xv_h); cudaGetSymbolAddress((void**)&Xvl, g_Xv_l);
    cudaGetSymbolAddress((void**)&Wqh, g_Wq_h); cudaGetSymbolAddress((void**)&Wql, g_Wq_l);
    cudaGetSymbolAddress((void**)&Wkh, g_Wk_h); cudaGetSymbolAddress((void**)&Wkl, g_Wk_l);
    cudaGetSymbolAddress((void**)&Wvh, g_Wv_h); cudaGetSymbolAddress((void**)&Wvl, g_Wv_l);
    cudaGetSymbolAddress((void**)&Qh,  g_Q_h);  cudaGetSymbolAddress((void**)&Ql,  g_Q_l);
    cudaGetSymbolAddress((void**)&Kh,  g_K_h);  cudaGetSymbolAddress((void**)&Kl,  g_K_l);
    cudaGetSymbolAddress((void**)&Vth, g_Vt_h); cudaGetSymbolAddress((void**)&Vtl, g_Vt_l);
    cudaGetSymbolAddress((void**)&Ph,  g_P_h);  cudaGetSymbolAddress((void**)&Pl,  g_P_l);
    cudaGetSymbolAddress((void**)&Sf,  g_S);

    cudaFuncSetAttribute(tc_gemm<0>, cudaFuncAttributeMaxDynamicSharedMemorySize, SMEM_TOTAL);
    cudaFuncSetAttribute(tc_gemm<1>, cudaFuncAttributeMaxDynamicSharedMemorySize, SMEM_TOTAL);
    cudaFuncSetAttribute(tc_gemm<2>, cudaFuncAttributeMaxDynamicSharedMemorySize, SMEM_TOTAL);

    // 1. split inputs & weights to bf16 hi/lo
    const int nX4 = (NTOK * DIN) / 4, nW4 = (DM * DIN) / 4;
    split_k<<<4096, 256>>>((const float4*)q,  Xqh, Xql, nX4);
    split_k<<<4096, 256>>>((const float4*)kx, Xkh, Xkl, nX4);
    split_k<<<4096, 256>>>((const float4*)vx, Xvh, Xvl, nX4);
    split_k<<<1024, 256>>>((const float4*)Wq, Wqh, Wql, nW4);
    split_k<<<1024, 256>>>((const float4*)Wk, Wkh, Wkl, nW4);
    split_k<<<1024, 256>>>((const float4*)Wv, Wvh, Wvl, nW4);

    // 2. projections (epilogue: split; V transposed)
    dim3 gP(DM / 128, NTOK / 128, 1);
    tc_gemm<1><<<gP, 256, SMEM_TOTAL>>>(Xqh, Xql, Wqh, Wql, bq,
                                        nullptr, Qh, Ql, DIN, DM, 1.0f, 0, 0, 0);
    tc_gemm<1><<<gP, 256, SMEM_TOTAL>>>(Xkh, Xkl, Wkh, Wkl, bk,
                                        nullptr, Kh, Kl, DIN, DM, 1.0f, 0, 0, 0);
    tc_gemm<2><<<gP, 256, SMEM_TOTAL>>>(Xvh, Xvl, Wvh, Wvl, bv,
                                        nullptr, Vth, Vtl, DIN, 0, 1.0f, 0, 0, 0);

    // 3. scores S = (Q K^T) / 32, batched
    dim3 gS(SEQ / 128, SEQ / 128, BN);
    tc_gemm<0><<<gS, 256, SMEM_TOTAL>>>(Qh, Ql, Kh, Kl, nullptr,
                                        Sf, nullptr, nullptr, DM, SEQ, 0.03125f,
                                        (size_t)SEQ * DM, (size_t)SEQ * DM,
                                        (size_t)SEQ * SEQ);

    // 4. softmax + split
    softmax_k<<<BN * SEQ, 256>>>(Sf, Ph, Pl);

    // 5. O = P * Vt^T, batched
    dim3 gO(DM / 128, SEQ / 128, BN);
    tc_gemm<0><<<gO, 256, SMEM_TOTAL>>>(Ph, Pl, Vth, Vtl, nullptr,
                                        out, nullptr, nullptr, SEQ, DM, 1.0f,
                                        (size_t)SEQ * SEQ, (size_t)DM * SEQ,
                                        (size_t)SEQ * DM);
}

// round 4
// speedup vs baseline: 5.5866x; 1.0740x over previous
#include <cuda_runtime.h>
#include <cuda_bf16.h>
#include <cstdint>

// ---------------------------------------------------------------------------
// Problem constants
// ---------------------------------------------------------------------------
#define BN   8
#define SEQ  2048
#define DIN  1024
#define DM   1024
#define NTOK (BN*SEQ)          // 16384

// ---------------------------------------------------------------------------
// Scratch (__device__ globals; allocation-free rule)
// ---------------------------------------------------------------------------
__device__ __nv_bfloat16 g_Xq_h[(size_t)NTOK*DIN];
__device__ __nv_bfloat16 g_Xq_l[(size_t)NTOK*DIN];
__device__ __nv_bfloat16 g_Xk_h[(size_t)NTOK*DIN];
__device__ __nv_bfloat16 g_Xk_l[(size_t)NTOK*DIN];
__device__ __nv_bfloat16 g_Xv_h[(size_t)NTOK*DIN];
__device__ __nv_bfloat16 g_Xv_l[(size_t)NTOK*DIN];
__device__ __nv_bfloat16 g_Wq_h[(size_t)DM*DIN];
__device__ __nv_bfloat16 g_Wq_l[(size_t)DM*DIN];
__device__ __nv_bfloat16 g_Wk_h[(size_t)DM*DIN];
__device__ __nv_bfloat16 g_Wk_l[(size_t)DM*DIN];
__device__ __nv_bfloat16 g_Wv_h[(size_t)DM*DIN];
__device__ __nv_bfloat16 g_Wv_l[(size_t)DM*DIN];
__device__ __nv_bfloat16 g_Q_h [(size_t)NTOK*DM];
__device__ __nv_bfloat16 g_Q_l [(size_t)NTOK*DM];
__device__ __nv_bfloat16 g_K_h [(size_t)NTOK*DM];
__device__ __nv_bfloat16 g_K_l [(size_t)NTOK*DM];
__device__ __nv_bfloat16 g_Vt_h[(size_t)BN*DM*SEQ];     // [b][v][s]
__device__ __nv_bfloat16 g_Vt_l[(size_t)BN*DM*SEQ];
__device__ float         g_S  [(size_t)BN*SEQ*SEQ];
__device__ __nv_bfloat16 g_P_h[(size_t)BN*SEQ*SEQ];
__device__ __nv_bfloat16 g_P_l[(size_t)BN*SEQ*SEQ];

// ---------------------------------------------------------------------------
// Helpers available on base compute_103
// ---------------------------------------------------------------------------
__device__ __forceinline__ uint32_t smem_u32(const void* p) {
    uint32_t a;
    asm("{ .reg .u64 t; cvta.to.shared.u64 t, %1; cvt.u32.u64 %0, t; }"
        : "=r"(a) : "l"(p));
    return a;
}
__device__ __forceinline__ void cp16(uint32_t dst, const void* src) {
    asm volatile("cp.async.cg.shared.global [%0], [%1], 16;" :: "r"(dst), "l"(src));
}
#define CP_COMMIT()  asm volatile("cp.async.commit_group;" ::: "memory")
#define CP_WAIT(N)   asm volatile("cp.async.wait_group %0;" :: "n"(N) : "memory")

__device__ __forceinline__ void mma16816(float* c, const uint32_t* a,
                                         uint32_t b0, uint32_t b1) {
    asm volatile(
        "mma.sync.aligned.m16n8k16.row.col.f32.bf16.bf16.f32 "
        "{%0,%1,%2,%3}, {%4,%5,%6,%7}, {%8,%9}, {%0,%1,%2,%3};"
        : "+f"(c[0]), "+f"(c[1]), "+f"(c[2]), "+f"(c[3])
        : "r"(a[0]), "r"(a[1]), "r"(a[2]), "r"(a[3]), "r"(b0), "r"(b1));
}

__device__ __forceinline__ void split2(float v, __nv_bfloat16& h, __nv_bfloat16& l) {
    h = __float2bfloat16(v);
    l = __float2bfloat16(v - __bfloat162float(h));
}

// ---------------------------------------------------------------------------
// tcgen05 helpers — ONLY compiled when the build has a compute_103a pass.
// ---------------------------------------------------------------------------
#if defined(__CUDA_ARCH_FEAT_SM103_ALL)
__device__ __forceinline__ uint32_t elect_one_pred() {
    uint32_t pred;
    asm volatile(
        "{\n\t.reg .pred p;\n\t"
        "elect.sync _|p, 0xFFFFFFFF;\n\t"
        "selp.b32 %0, 1, 0, p;\n\t}"
        : "=r"(pred));
    return pred;
}
#define MBARRIER_INIT(addr, cnt) \
    asm volatile("mbarrier.init.shared.b64 [%0], %1;" :: "r"((uint32_t)(addr)), "r"((uint32_t)(cnt)) : "memory")
#define MBARRIER_WAIT_PARITY(mbar, par) do { \
    uint32_t _m = (uint32_t)(mbar), _p = (uint32_t)(par), _d; \
    asm volatile("{\n\t.reg .pred p;\n\t" \
        "mbarrier.try_wait.parity.acquire.cta.shared::cta.b64 p, [%1], %2;\n\t" \
        "selp.b32 %0, 1, 0, p;\n\t}" : "=r"(_d) : "r"(_m), "r"(_p) : "memory"); \
    if (!_d) { \
        asm volatile("{\n\t.reg .pred P1;\n\t" \
            "WL_%=:\n\t" \
            "mbarrier.try_wait.parity.acquire.cta.shared::cta.b64 P1, [%0], %1, 0x989680;\n\t" \
            "@P1 bra.uni WD_%=;\n\tbra.uni WL_%=;\n\tWD_%=:\n\t}" \
            :: "r"(_m), "r"(_p) : "memory"); \
    } \
} while (0)
#define TCGEN05_ALLOC(a, n) \
    asm volatile("tcgen05.alloc.cta_group::1.sync.aligned.shared::cta.b32 [%0], %1;" \
        :: "r"((uint32_t)(a)), "r"((uint32_t)(n)) : "memory")
#define TCGEN05_RELINQUISH() \
    asm volatile("tcgen05.relinquish_alloc_permit.cta_group::1.sync.aligned;")
#define TCGEN05_DEALLOC(t, n) \
    asm volatile("tcgen05.dealloc.cta_group::1.sync.aligned.b32 %0, %1;" :: "r"(t), "r"((uint32_t)(n)))
#define TCGEN05_COMMIT(m) \
    asm volatile("tcgen05.commit.cta_group::1.mbarrier::arrive::one.shared::cluster.b64 [%0];" \
        :: "r"((uint32_t)(m)) : "memory")
#define TCGEN05_WAIT_LD()    asm volatile("tcgen05.wait::ld.sync.aligned;" ::: "memory")
#define TCGEN05_FENCE_AFTER() asm volatile("tcgen05.fence::after_thread_sync;" ::: "memory")
#define FENCE_PROXY_ASYNC()  asm volatile("fence.proxy.async.shared::cta;" ::: "memory")
#define TCGEN05_LD_32X32B_X32(r, ta) \
    asm volatile( \
        "tcgen05.ld.sync.aligned.32x32b.x32.b32 " \
        "{%0, %1, %2, %3, %4, %5, %6, %7, " \
        " %8, %9, %10, %11, %12, %13, %14, %15, " \
        " %16, %17, %18, %19, %20, %21, %22, %23, " \
        " %24, %25, %26, %27, %28, %29, %30, %31}, [%32];" \
        : "=r"((r)[0]),  "=r"((r)[1]),  "=r"((r)[2]),  "=r"((r)[3]), \
          "=r"((r)[4]),  "=r"((r)[5]),  "=r"((r)[6]),  "=r"((r)[7]), \
          "=r"((r)[8]),  "=r"((r)[9]),  "=r"((r)[10]), "=r"((r)[11]), \
          "=r"((r)[12]), "=r"((r)[13]), "=r"((r)[14]), "=r"((r)[15]), \
          "=r"((r)[16]), "=r"((r)[17]), "=r"((r)[18]), "=r"((r)[19]), \
          "=r"((r)[20]), "=r"((r)[21]), "=r"((r)[22]), "=r"((r)[23]), \
          "=r"((r)[24]), "=r"((r)[25]), "=r"((r)[26]), "=r"((r)[27]), \
          "=r"((r)[28]), "=r"((r)[29]), "=r"((r)[30]), "=r"((r)[31]) \
        : "r"(ta))
static constexpr uint64_t SMEM_DESC_BASE_SW128 =
    (uint64_t(2)  << 61) | (uint64_t(1) << 46) | (uint64_t(64) << 32) | (uint64_t(1) << 16);
#define MAKE_SMEM_DESC(ba) (SMEM_DESC_BASE_SW128 | ((uint64_t)((ba) >> 4) & 0x3FFF))
#define SWZ128(off) ((off) ^ (((off) >> 3) & 0x70))
__device__ __forceinline__ void mma_bf16_ss(uint32_t d, uint64_t ad, uint64_t bd,
                                            uint32_t idesc, bool acc) {
    uint32_t en = acc ? 1u : 0u;
    asm volatile(
        "{\n\t.reg .pred p;\n\t"
        "setp.ne.u32 p, %5, 0;\n\t"
        "tcgen05.mma.cta_group::1.kind::f16 [%0], %1, %2, %3, {%4, %4, %4, %4}, p;\n\t"
        "}"
        :: "r"(d), "l"(ad), "l"(bd), "r"(idesc), "r"(0u), "r"(en)
        : "memory");
}
#endif  // __CUDA_ARCH_FEAT_SM103_ALL

// ---------------------------------------------------------------------------
// GEMM: C[M,N] = alpha * A[M,K] * B[N,K]^T (+bias), split-bf16 3-pass:
//   acc = Ah*Bh + Ah*Bl + Al*Bh      (AlBl dropped, ~2^-16 rel)
// CTA tile 128(M) x 256(N), K-chunk 64, 256 threads, grid (N/256, M/128, batch)
// MODE 0: f32 out (alpha)   MODE 1: split bf16 out (+bias)
// MODE 2: split bf16 transposed out (+bias), V -> Vt[b][n][s]
// Body dispatches on arch: tcgen05 (sm_103a cubin) vs mma.sync (base).
// ---------------------------------------------------------------------------
constexpr int TM = 128, TN = 256, TK = 64;
constexpr int OFF_AH = 0;
constexpr int OFF_AL = 16384;
constexpr int OFF_BH = 32768;
constexpr int OFF_BL = 65536;
constexpr int STAGE  = 98304;     // (128+256)*128B*2(hi/lo)
constexpr int SMEM_TOTAL = 1024 + 2 * STAGE;   // 197632

template <int MODE>
__global__ void __launch_bounds__(256, 1) tc_gemm(
    const __nv_bfloat16* __restrict__ Ah, const __nv_bfloat16* __restrict__ Al,
    const __nv_bfloat16* __restrict__ Bh, const __nv_bfloat16* __restrict__ Bl,
    const float* __restrict__ bias,
    float* __restrict__ Cf,
    __nv_bfloat16* __restrict__ Ch, __nv_bfloat16* __restrict__ Cl,
    int K, int ldc, float alpha,
    size_t sA, size_t sB, size_t sC)
{
    extern __shared__ char smem[];
    const int tid   = threadIdx.x;
    const size_t zb = blockIdx.z;
    const int m0    = blockIdx.y * TM;
    const int n0    = blockIdx.x * TN;
    Ah += zb * sA;  Al += zb * sA;
    Bh += zb * sB;  Bl += zb * sB;

#if defined(__CUDA_ARCH_FEAT_SM103_ALL)
    // ======================= tcgen05 path (sm_103a) ========================
    const uint32_t sb = smem_u32(smem);

    if (tid < 32) TCGEN05_ALLOC(sb + 0, 256);
    if (tid >= 32 && tid < 64) TCGEN05_RELINQUISH();
    if (tid == 0) { MBARRIER_INIT(sb + 8, 1); MBARRIER_INIT(sb + 16, 1); }
    __syncthreads();
    uint32_t tmem;
    asm volatile("ld.shared.b32 %0, [%1];" : "=r"(tmem) : "r"(sb + 0));

    const int col = tid & 7;       // 16B block within 128B row
    const int rg  = tid >> 3;      // 0..31

    auto load_chunk = [&](int kc, int st) {
        const uint32_t base = sb + 1024 + st * STAGE;
        const size_t koff = (size_t)kc * TK + col * 8;
        const __nv_bfloat16* pah = Ah + (size_t)(m0 + rg) * K + koff;
        const __nv_bfloat16* pal = Al + (size_t)(m0 + rg) * K + koff;
        const __nv_bfloat16* pbh = Bh + (size_t)(n0 + rg) * K + koff;
        const __nv_bfloat16* pbl = Bl + (size_t)(n0 + rg) * K + koff;
#pragma unroll
        for (int i = 0; i < TM / 32; ++i) {          // A: 128 rows
            uint32_t so = SWZ128((rg + 32 * i) * 128 + col * 16);
            cp16(base + OFF_AH + so, pah + (size_t)(32 * i) * K);
            cp16(base + OFF_AL + so, pal + (size_t)(32 * i) * K);
        }
#pragma unroll
        for (int i = 0; i < TN / 32; ++i) {          // B: 256 rows
            uint32_t so = SWZ128((rg + 32 * i) * 128 + col * 16);
            cp16(base + OFF_BH + so, pbh + (size_t)(32 * i) * K);
            cp16(base + OFF_BL + so, pbl + (size_t)(32 * i) * K);
        }
    };

    constexpr uint32_t IDESC =
        (1u << 4) | (1u << 7) | (1u << 10) | ((TN / 8) << 17) | ((TM / 16) << 24);
    const int NC = K / TK;

    load_chunk(0, 0); CP_COMMIT();
    load_chunk(1, 1); CP_COMMIT();

    int ph[2] = {0, 0};
    for (int c = 0; c < NC; ++c) {
        const int st = c & 1;
        if (c + 1 < NC) { CP_WAIT(1); } else { CP_WAIT(0); }
        FENCE_PROXY_ASYNC();
        __syncthreads();

        if (tid < 32 && elect_one_pred()) {
            TCGEN05_FENCE_AFTER();
            const uint32_t base = sb + 1024 + st * STAGE;
            const uint64_t dah = MAKE_SMEM_DESC(base + OFF_AH);
            const uint64_t dal = MAKE_SMEM_DESC(base + OFF_AL);
            const uint64_t dbh = MAKE_SMEM_DESC(base + OFF_BH);
            const uint64_t dbl = MAKE_SMEM_DESC(base + OFF_BL);
#pragma unroll
            for (int ks = 0; ks < 4; ++ks)
                mma_bf16_ss(tmem, dah + ks * 2, dbh + ks * 2, IDESC, !(c == 0 && ks == 0));
#pragma unroll
            for (int ks = 0; ks < 4; ++ks)
                mma_bf16_ss(tmem, dah + ks * 2, dbl + ks * 2, IDESC, true);
#pragma unroll
            for (int ks = 0; ks < 4; ++ks)
                mma_bf16_ss(tmem, dal + ks * 2, dbh + ks * 2, IDESC, true);
            TCGEN05_COMMIT(sb + 8 + 8 * st);
        }
        MBARRIER_WAIT_PARITY(sb + 8 + 8 * st, ph[st]);
        ph[st] ^= 1;
        if (c + 2 < NC) { load_chunk(c + 2, st); CP_COMMIT(); }
    }
    TCGEN05_FENCE_AFTER();

    if (tid < 128) {
        const int w = tid >> 5, lid = tid & 31;
        const int m = m0 + w * 32 + lid;
        for (int j0 = 0; j0 < TN; j0 += 32) {
            uint32_t r[32];
            TCGEN05_LD_32X32B_X32(r, tmem + j0);
            TCGEN05_WAIT_LD();
            if (MODE == 0) {
                float4* dst = (float4*)(Cf + zb * sC + (size_t)m * ldc + n0 + j0);
#pragma unroll
                for (int i = 0; i < 8; ++i) {
                    float4 v;
                    v.x = __uint_as_float(r[4 * i + 0]) * alpha;
                    v.y = __uint_as_float(r[4 * i + 1]) * alpha;
                    v.z = __uint_as_float(r[4 * i + 2]) * alpha;
                    v.w = __uint_as_float(r[4 * i + 3]) * alpha;
                    dst[i] = v;
                }
            } else if (MODE == 1) {
                const size_t rb = (size_t)m * ldc + n0 + j0;
#pragma unroll
                for (int i = 0; i < 32; i += 2) {
                    float v0 = __uint_as_float(r[i])     + bias[n0 + j0 + i];
                    float v1 = __uint_as_float(r[i + 1]) + bias[n0 + j0 + i + 1];
                    __nv_bfloat16 h0, l0, h1, l1;
                    split2(v0, h0, l0); split2(v1, h1, l1);
                    __nv_bfloat162 hp; hp.x = h0; hp.y = h1;
                    __nv_bfloat162 lp; lp.x = l0; lp.y = l1;
                    *(__nv_bfloat162*)(Ch + rb + i) = hp;
                    *(__nv_bfloat162*)(Cl + rb + i) = lp;
                }
            } else {
                const int b  = m >> 11;
                const int sx = m & 2047;
                const size_t bb = (size_t)b * DM * SEQ;
#pragma unroll
                for (int i = 0; i < 32; ++i) {
                    const int n = n0 + j0 + i;
                    float v = __uint_as_float(r[i]) + bias[n];
                    __nv_bfloat16 h, l;
                    split2(v, h, l);
                    Ch[bb + (size_t)n * SEQ + sx] = h;
                    Cl[bb + (size_t)n * SEQ + sx] = l;
                }
            }
        }
    }
    __syncthreads();
    if (tid < 32) TCGEN05_DEALLOC(tmem, 256);

#elif defined(__CUDA_ARCH__)
    // ================= mma.sync fallback (base compute_103) =================
    // Processes the 256-wide N tile as two sequential 128-wide halves.
    constexpr int STR = 20;                 // words per 32-bf16 row (padded)
    constexpr int TILE_W = 128 * STR;       // 2560 words
    constexpr int STAGE_W = 4 * TILE_W;     // 10240 words
    const uint32_t sbase = smem_u32(smem);
    const int lane = tid & 31, wid = tid >> 5;
    const int wm = wid >> 1, wn = wid & 1;
    const int g = lane >> 2, tg = lane & 3;

    auto load_chunk = [&](int kc, int st, int nbase) {
        const int q = tid & 3, r0 = tid >> 2;
        const uint32_t dst0 = sbase + st * STAGE_W * 4;
        const size_t koff = (size_t)kc * 32 + q * 8;
#pragma unroll
        for (int i = 0; i < 2; ++i) {
            const int r = r0 + 64 * i;
            const uint32_t ro = (uint32_t)(r * STR + q * 4) * 4;
            cp16(dst0 + 0 * TILE_W * 4 + ro, Ah + (size_t)(m0 + r) * K + koff);
            cp16(dst0 + 1 * TILE_W * 4 + ro, Al + (size_t)(m0 + r) * K + koff);
            cp16(dst0 + 2 * TILE_W * 4 + ro, Bh + (size_t)(nbase + r) * K + koff);
            cp16(dst0 + 3 * TILE_W * 4 + ro, Bl + (size_t)(nbase + r) * K + koff);
        }
    };

    for (int np = 0; np < 2; ++np) {
        const int nb0 = n0 + np * 128;

        float acc[2][8][4];
#pragma unroll
        for (int a = 0; a < 2; ++a)
#pragma unroll
            for (int b = 0; b < 8; ++b)
#pragma unroll
                for (int c = 0; c < 4; ++c) acc[a][b][c] = 0.0f;

        const int NC = K / 32;
        load_chunk(0, 0, nb0); CP_COMMIT();

        for (int c = 0; c < NC; ++c) {
            const int st = c & 1;
            if (c + 1 < NC) { load_chunk(c + 1, st ^ 1, nb0); CP_COMMIT(); CP_WAIT(1); }
            else            { CP_WAIT(0); }
            __syncthreads();

            const uint32_t* s0 = (const uint32_t*)smem + st * STAGE_W;
#pragma unroll
            for (int ks = 0; ks < 2; ++ks) {
                uint32_t ahf[2][4], alf[2][4];
#pragma unroll
                for (int mt = 0; mt < 2; ++mt) {
                    const int rb = wm * 32 + mt * 16;
                    const uint32_t* pa = s0 + (rb + g) * STR + ks * 8 + tg;
                    ahf[mt][0] = pa[0];           ahf[mt][2] = pa[4];
                    ahf[mt][1] = pa[8 * STR];     ahf[mt][3] = pa[8 * STR + 4];
                    const uint32_t* pl = pa + TILE_W;
                    alf[mt][0] = pl[0];           alf[mt][2] = pl[4];
                    alf[mt][1] = pl[8 * STR];     alf[mt][3] = pl[8 * STR + 4];
                }
#pragma unroll
                for (int nt = 0; nt < 8; ++nt) {
                    const int nb = wn * 64 + nt * 8;
                    const uint32_t* pb = s0 + 2 * TILE_W + (nb + g) * STR + ks * 8 + tg;
                    const uint32_t bh0 = pb[0], bh1 = pb[4];
                    const uint32_t* pbl = pb + TILE_W;
                    const uint32_t bl0 = pbl[0], bl1 = pbl[4];
#pragma unroll
                    for (int mt = 0; mt < 2; ++mt) {
                        mma16816(acc[mt][nt], ahf[mt], bh0, bh1);
                        mma16816(acc[mt][nt], ahf[mt], bl0, bl1);
                        mma16816(acc[mt][nt], alf[mt], bh0, bh1);
                    }
                }
            }
            __syncthreads();
        }

#pragma unroll
        for (int mt = 0; mt < 2; ++mt) {
#pragma unroll
            for (int nt = 0; nt < 8; ++nt) {
                const int m1 = m0 + wm * 32 + mt * 16 + g;
                const int m2 = m1 + 8;
                const int n  = nb0 + wn * 64 + nt * 8 + tg * 2;
                const float* a = acc[mt][nt];
                if (MODE == 0) {
                    float2 v0; v0.x = a[0] * alpha; v0.y = a[1] * alpha;
                    float2 v1; v1.x = a[2] * alpha; v1.y = a[3] * alpha;
                    *(float2*)(Cf + zb * sC + (size_t)m1 * ldc + n) = v0;
                    *(float2*)(Cf + zb * sC + (size_t)m2 * ldc + n) = v1;
                } else if (MODE == 1) {
                    const float b0 = bias[n], b1 = bias[n + 1];
                    __nv_bfloat16 h0, l0, h1, l1;
                    split2(a[0] + b0, h0, l0); split2(a[1] + b1, h1, l1);
                    __nv_bfloat162 hp; hp.x = h0; hp.y = h1;
                    __nv_bfloat162 lp; lp.x = l0; lp.y = l1;
                    *(__nv_bfloat162*)(Ch + (size_t)m1 * ldc + n) = hp;
                    *(__nv_bfloat162*)(Cl + (size_t)m1 * ldc + n) = lp;
                    split2(a[2] + b0, h0, l0); split2(a[3] + b1, h1, l1);
                    hp.x = h0; hp.y = h1; lp.x = l0; lp.y = l1;
                    *(__nv_bfloat162*)(Ch + (size_t)m2 * ldc + n) = hp;
                    *(__nv_bfloat162*)(Cl + (size_t)m2 * ldc + n) = lp;
                } else {
                    const float b0 = bias[n], b1 = bias[n + 1];
#pragma unroll
                    for (int e = 0; e < 4; ++e) {
                        const int m = (e < 2) ? m1 : m2;
                        const int nn = n + (e & 1);
                        const float bb_ = (e & 1) ? b1 : b0;
                        const int bidx = m >> 11, sx = m & 2047;
                        __nv_bfloat16 h, l;
                        split2(a[e] + bb_, h, l);
                        const size_t off = (size_t)bidx * DM * SEQ + (size_t)nn * SEQ + sx;
                        Ch[off] = h;
                        Cl[off] = l;
                    }
                }
            }
        }
        __syncthreads();
    }
#endif
}

// ---------------------------------------------------------------------------
// f32 -> bf16 hi/lo split
// ---------------------------------------------------------------------------
__global__ void __launch_bounds__(256) split_k(
    const float4* __restrict__ x,
    __nv_bfloat16* __restrict__ h, __nv_bfloat16* __restrict__ l, int n4)
{
    for (int i = blockIdx.x * 256 + threadIdx.x; i < n4; i += gridDim.x * 256) {
        float4 v = x[i];
        __nv_bfloat16 h0, l0, h1, l1, h2, l2, h3, l3;
        split2(v.x, h0, l0); split2(v.y, h1, l1);
        split2(v.z, h2, l2); split2(v.w, h3, l3);
        __nv_bfloat162 ha; ha.x = h0; ha.y = h1;
        __nv_bfloat162 hb; hb.x = h2; hb.y = h3;
        __nv_bfloat162 la; la.x = l0; la.y = l1;
        __nv_bfloat162 lb; lb.x = l2; lb.y = l3;
        *(__nv_bfloat162*)(h + 4 * (size_t)i)     = ha;
        *(__nv_bfloat162*)(h + 4 * (size_t)i + 2) = hb;
        *(__nv_bfloat162*)(l + 4 * (size_t)i)     = la;
        *(__nv_bfloat162*)(l + 4 * (size_t)i + 2) = lb;
    }
}

// ---------------------------------------------------------------------------
// Row softmax over SEQ, emitting split bf16 P
// ---------------------------------------------------------------------------
__global__ void __launch_bounds__(256) softmax_k(
    const float* __restrict__ S,
    __nv_bfloat16* __restrict__ Ph, __nv_bfloat16* __restrict__ Pl)
{
    const float* p = S + (size_t)blockIdx.x * SEQ;
    const int tid = threadIdx.x;

    float v[8];
    float mx = -1e30f;
#pragma unroll
    for (int i = 0; i < 8; ++i) { v[i] = p[tid + i * 256]; mx = fmaxf(mx, v[i]); }

    __shared__ float redm[8], reds[8];
#pragma unroll
    for (int o = 16; o > 0; o >>= 1)
        mx = fmaxf(mx, __shfl_xor_sync(0xffffffffu, mx, o));
    if ((tid & 31) == 0) redm[tid >> 5] = mx;
    __syncthreads();
    mx = redm[0];
#pragma unroll
    for (int i = 1; i < 8; ++i) mx = fmaxf(mx, redm[i]);

    float s = 0.0f;
#pragma unroll
    for (int i = 0; i < 8; ++i) { v[i] = __expf(v[i] - mx); s += v[i]; }
#pragma unroll
    for (int o = 16; o > 0; o >>= 1)
        s += __shfl_xor_sync(0xffffffffu, s, o);
    if ((tid & 31) == 0) reds[tid >> 5] = s;
    __syncthreads();
    s = 0.0f;
#pragma unroll
    for (int i = 0; i < 8; ++i) s += reds[i];

    const float inv = 1.0f / s;
    size_t rb = (size_t)blockIdx.x * SEQ;
#pragma unroll
    for (int i = 0; i < 8; ++i) {
        __nv_bfloat16 h, l;
        split2(v[i] * inv, h, l);
        Ph[rb + tid + i * 256] = h;
        Pl[rb + tid + i * 256] = l;
    }
}

// ---------------------------------------------------------------------------
extern "C" void kernel_launch(void* const* d_in, const int* in_sizes, int n_in,
                              void* d_out, int out_size)
{
    (void)in_sizes; (void)n_in; (void)out_size;
    const float* q  = (const float*)d_in[0];
    const float* kx = (const float*)d_in[1];
    const float* vx = (const float*)d_in[2];
    const float* Wq = (const float*)d_in[3];
    const float* bq = (const float*)d_in[4];
    const float* Wk = (const float*)d_in[5];
    const float* bk = (const float*)d_in[6];
    const float* Wv = (const float*)d_in[7];
    const float* bv = (const float*)d_in[8];
    float* out = (float*)d_out;

    __nv_bfloat16 *Xqh, *Xql, *Xkh, *Xkl, *Xvh, *Xvl;
    __nv_bfloat16 *Wqh, *Wql, *Wkh, *Wkl, *Wvh, *Wvl;
    __nv_bfloat16 *Qh, *Ql, *Kh, *Kl, *Vth, *Vtl, *Ph, *Pl;
    float* Sf;
    cudaGetSymbolAddress((void**)&Xqh, g_Xq_h); cudaGetSymbolAddress((void**)&Xql, g_Xq_l);
    cudaGetSymbolAddress((void**)&Xkh, g_Xk_h); cudaGetSymbolAddress((void**)&Xkl, g_Xk_l);
    cudaGetSymbolAddress((void**)&Xvh, g_Xv_h); cudaGetSymbolAddress((void**)&Xvl, g_Xv_l);
    cudaGetSymbolAddress((void**)&Wqh, g_Wq_h); cudaGetSymbolAddress((void**)&Wql, g_Wq_l);
    cudaGetSymbolAddress((void**)&Wkh, g_Wk_h); cudaGetSymbolAddress((void**)&Wkl, g_Wk_l);
    cudaGetSymbolAddress((void**)&Wvh, g_Wv_h); cudaGetSymbolAddress((void**)&Wvl, g_Wv_l);
    cudaGetSymbolAddress((void**)&Qh,  g_Q_h);  cudaGetSymbolAddress((void**)&Ql,  g_Q_l);
    cudaGetSymbolAddress((void**)&Kh,  g_K_h);  cudaGetSymbolAddress((void**)&Kl,  g_K_l);
    cudaGetSymbolAddress((void**)&Vth, g_Vt_h); cudaGetSymbolAddress((void**)&Vtl, g_Vt_l);
    cudaGetSymbolAddress((void**)&Ph,  g_P_h);  cudaGetSymbolAddress((void**)&Pl,  g_P_l);
    cudaGetSymbolAddress((void**)&Sf,  g_S);

    cudaFuncSetAttribute(tc_gemm<0>, cudaFuncAttributeMaxDynamicSharedMemorySize, SMEM_TOTAL);
    cudaFuncSetAttribute(tc_gemm<1>, cudaFuncAttributeMaxDynamicSharedMemorySize, SMEM_TOTAL);
    cudaFuncSetAttribute(tc_gemm<2>, cudaFuncAttributeMaxDynamicSharedMemorySize, SMEM_TOTAL);

    // 1. split inputs & weights to bf16 hi/lo
    const int nX4 = (NTOK * DIN) / 4, nW4 = (DM * DIN) / 4;
    split_k<<<4096, 256>>>((const float4*)q,  Xqh, Xql, nX4);
    split_k<<<4096, 256>>>((const float4*)kx, Xkh, Xkl, nX4);
    split_k<<<4096, 256>>>((const float4*)vx, Xvh, Xvl, nX4);
    split_k<<<1024, 256>>>((const float4*)Wq, Wqh, Wql, nW4);
    split_k<<<1024, 256>>>((const float4*)Wk, Wkh, Wkl, nW4);
    split_k<<<1024, 256>>>((const float4*)Wv, Wvh, Wvl, nW4);

    // 2. projections (epilogue: split; V transposed)
    dim3 gP(DM / TN, NTOK / TM, 1);
    tc_gemm<1><<<gP, 256, SMEM_TOTAL>>>(Xqh, Xql, Wqh, Wql, bq,
                                        nullptr, Qh, Ql, DIN, DM, 1.0f, 0, 0, 0);
    tc_gemm<1><<<gP, 256, SMEM_TOTAL>>>(Xkh, Xkl, Wkh, Wkl, bk,
                                        nullptr, Kh, Kl, DIN, DM, 1.0f, 0, 0, 0);
    tc_gemm<2><<<gP, 256, SMEM_TOTAL>>>(Xvh, Xvl, Wvh, Wvl, bv,
                                        nullptr, Vth, Vtl, DIN, 0, 1.0f, 0, 0, 0);

    // 3. scores S = (Q K^T) / 32, batched
    dim3 gS(SEQ / TN, SEQ / TM, BN);
    tc_gemm<0><<<gS, 256, SMEM_TOTAL>>>(Qh, Ql, Kh, Kl, nullptr,
                                        Sf, nullptr, nullptr, DM, SEQ, 0.03125f,
                                        (size_t)SEQ * DM, (size_t)SEQ * DM,
                                        (size_t)SEQ * SEQ);

    // 4. softmax + split
    softmax_k<<<BN * SEQ, 256>>>(Sf, Ph, Pl);

    // 5. O = P * Vt^T, batched
    dim3 gO(DM / TN, SEQ / TM, BN);
    tc_gemm<0><<<gO, 256, SMEM_TOTAL>>>(Ph, Pl, Vth, Vtl, nullptr,
                                        out, nullptr, nullptr, SEQ, DM, 1.0f,
                                        (size_t)SEQ * SEQ, (size_t)DM * SEQ,
                                        (size_t)SEQ * DM);
}